// round 16
// baseline (speedup 1.0000x reference)
#include <cuda_runtime.h>
#include <cuda_bf16.h>

// diag-embed: out[i, j, k] = (j == k) ? x[i, j] : 0
// x: [8192, 176] fp32, out: [8192, 176, 176] fp32 (~1.015 GB of stores).
//
// FINAL champion (R4; re-validated R10/R12/R13/R14/R15, profile bit-stable:
// kernel 157.7-158.7us, DRAM 76.3-76.8%). 1.015 GB / ~158us = 6.4 TB/s
// sustained — the measured pure-write HBM ceiling of this GB300.
// Load-bearing properties, each falsification-tested across 15 rounds:
//   - 1184 blocks x 256 threads = 8 blocks/SM, 2048 thr/SM (~97% occ),
//     fine-grained whole-grid interleaved store stream
//     (beat slabs R7, warp-tiles R8; packing-invariant R12)
//   - branchless diagonal insertion: unconditional L2-hot LDG + 4 selects
//     (beat divergent branch R1-R3; LDG is 1 instr/warp, 1-2 hot sectors)
//   - 32-bit magic div/mod (indexing never binding: R6, R8, R11)
//   - __stcs STG.128 lane-consecutive (beat STG.256 R11 — wider stores
//     REDUCED DRAM%; cs==wt R9; fused beats fill+scatter by 70us R8)
//   - unroll 8 (16 is compiler-equivalent, R15)

#define D_MODEL 176u
#define CPR 44u            // float4 chunks per output row
#define BLOCKS 1184u       // 148 SMs * 8 blocks -> perfectly balanced
#define THREADS 256u

__global__ __launch_bounds__(THREADS) void diag_embed_kernel(
        const float* __restrict__ x,
        float4* __restrict__ out,
        unsigned n4) {
    const unsigned stride = BLOCKS * THREADS;
    unsigned g = blockIdx.x * THREADS + threadIdx.x;

    #pragma unroll 8
    for (; g < n4; g += stride) {
        unsigned rowg = g / CPR;                 // 32-bit magic div
        unsigned q    = g - rowg * CPR;          // chunk within row
        unsigned row  = rowg % D_MODEL;          // diag position in row

        // Unconditional: warp's chunks span <=2 rows -> 1-2 L2-hot sectors.
        float xv = __ldg(x + rowg);

        unsigned c0 = q * 4u;                    // column of v.x
        float4 v;
        v.x = (c0        == row) ? xv : 0.f;
        v.y = (c0 + 1u   == row) ? xv : 0.f;
        v.z = (c0 + 2u   == row) ? xv : 0.f;
        v.w = (c0 + 3u   == row) ? xv : 0.f;

        __stcs(out + g, v);                      // streaming store
    }
}

extern "C" void kernel_launch(void* const* d_in, const int* in_sizes, int n_in,
                              void* d_out, int out_size) {
    const float* x = (const float*)d_in[0];
    float4* out = (float4*)d_out;

    unsigned n4 = (unsigned)(out_size / 4);      // 63,438,848 float4 chunks

    diag_embed_kernel<<<BLOCKS, THREADS>>>(x, out, n4);
}

// round 17
// speedup vs baseline: 1.0134x; 1.0134x over previous
#include <cuda_runtime.h>
#include <cuda_bf16.h>

// diag-embed: out[i, j, k] = (j == k) ? x[i, j] : 0
// x: [8192, 176] fp32, out: [8192, 176, 176] fp32 (~1.015 GB of stores).
//
// R17: store-width series completion. Measured so far:
//   STG.256 -> 73.3% DRAM (R11), STG.128 -> 76.4% DRAM (champion R4).
// Hypothesis from R11: the DRAM write path favors MORE, SMALLER in-flight
// transactions. Test STG.64: one 8B __stcs per lane per iteration, lanes
// consecutive (warp = 256 contiguous bytes/instr, fully coalesced), 2x the
// store instructions of the champion (issue 28% -> ~45%, still headroom).
// All other champion properties frozen (1184 x 256, branchless selects,
// 32-bit magic div/mod, one L2-hot LDG per chunk, unroll 8).

#define D_MODEL 176u
#define HPR 88u            // float2 (8B) chunks per output row (176/2)
#define BLOCKS 1184u       // 148 SMs * 8 blocks
#define THREADS 256u

__global__ __launch_bounds__(THREADS) void diag_embed_kernel(
        const float* __restrict__ x,
        float2* __restrict__ out,
        unsigned n8) {
    const unsigned stride = BLOCKS * THREADS;
    unsigned h = blockIdx.x * THREADS + threadIdx.x;

    #pragma unroll 8
    for (; h < n8; h += stride) {
        unsigned rowg = h / HPR;                 // 32-bit magic div
        unsigned q8   = h - rowg * HPR;          // 8B-chunk within row
        unsigned row  = rowg % D_MODEL;          // diag position in row

        float xv = __ldg(x + rowg);              // L1/L2-hot (x = 5.8 MB)

        unsigned c0 = q8 * 2u;                   // column of v.x
        float2 v;
        v.x = (c0      == row) ? xv : 0.f;
        v.y = (c0 + 1u == row) ? xv : 0.f;

        __stcs(out + h, v);                      // STG.64, lanes consecutive
    }
}

extern "C" void kernel_launch(void* const* d_in, const int* in_sizes, int n_in,
                              void* d_out, int out_size) {
    const float* x = (const float*)d_in[0];
    float2* out = (float2*)d_out;

    unsigned n8 = (unsigned)(out_size / 2);      // 126,877,696 8B chunks

    diag_embed_kernel<<<BLOCKS, THREADS>>>(x, out, n8);
}